// round 13
// baseline (speedup 1.0000x reference)
#include <cuda_runtime.h>

#define S_DIM 256
#define H_DIM 256
#define W_DIM 256
#define F_DIM 6
#define B_DIM 4096
#define NQ (B_DIM * 4)          // 16384 queries, q = b*4 + t*2 + es
#define NBIN 16384              // sort key = (x<<6) | (y>>2): 4-cell (96B) bins
#define S_STRIDE (H_DIM * W_DIM * F_DIM)

__device__ int   g_bin[NBIN];   // static zero-init; k_sortfin re-zeroes each call
__device__ int   g_off[NBIN];
__device__ int   g_keys[NQ];
__device__ int   g_perm[NQ];
__device__ float g_qv[NQ];
__device__ int   g_done[B_DIM]; // static zero-init; reset by the 4th arriver

__device__ __forceinline__ int query_key(const float* __restrict__ phi, int q) {
    const int b  = q >> 2;
    const int t  = (q >> 1) & 1;
    const int es = q & 1;
    const float* p = phi + b * 20 + t * 10;
    const int x = (int)p[6 + 2 * es];
    const int y = (int)p[7 + 2 * es];
    return (x << 6) | (y >> 2);
}

// ---------- phase A: keys + global histogram ----------
__global__ __launch_bounds__(128)
void k_hist(const float* __restrict__ phi) {
    const int q = blockIdx.x * 128 + threadIdx.x;
    const int key = query_key(phi, q);
    g_keys[q] = key;
    atomicAdd(&g_bin[key], 1);
}

// ---------- phase B: fused scan + scatter, one block (offsets in global) ----------
__global__ __launch_bounds__(1024)
void k_sortfin() {
    __shared__ int wsum[32];
    const int tid  = threadIdx.x;
    const int lane = tid & 31;
    const int wid  = tid >> 5;
    const int base = tid * 16;

    int c[16];
    int tsum = 0;
#pragma unroll
    for (int u = 0; u < 16; u++) { c[u] = g_bin[base + u]; tsum += c[u]; }

    int incl = tsum;
#pragma unroll
    for (int off = 1; off < 32; off <<= 1) {
        const int n = __shfl_up_sync(0xffffffffu, incl, off);
        if (lane >= off) incl += n;
    }
    if (lane == 31) wsum[wid] = incl;
    __syncthreads();
    if (wid == 0) {
        const int v = wsum[lane];
        int iv = v;
#pragma unroll
        for (int off = 1; off < 32; off <<= 1) {
            const int n = __shfl_up_sync(0xffffffffu, iv, off);
            if (lane >= off) iv += n;
        }
        wsum[lane] = iv - v;
    }
    __syncthreads();

    int run = incl - tsum + wsum[wid];
#pragma unroll
    for (int u = 0; u < 16; u++) {
        g_off[base + u] = run;   // running offsets live in global (16K bins)
        run += c[u];
        g_bin[base + u] = 0;     // restore invariant for the next graph replay
    }
    __syncthreads();
    __threadfence_block();

    // scatter: 16 queries per thread; spread global atomics (one per bin slot)
#pragma unroll
    for (int u = 0; u < 16; u++) {
        const int q   = tid + u * 1024;
        const int pos = atomicAdd(&g_off[g_keys[q]], 1);
        g_perm[pos] = q;
    }
}

// ---------- main gather: warp = 4 consecutive sorted queries x 8 s-lanes ----------
// (round-7 measured-best shape + 16384-bin key) lane = ql*8 + k; thread owns
// s = 32k + j. Sorted same-line queries share one load instruction -> the
// warp coalescer merges them into ~1 line request per plane step.
__global__ __launch_bounds__(128, 8)
void k_main(const float* __restrict__ phi,
            const float* __restrict__ w_lin,
            const float* __restrict__ succ,
            float* __restrict__ out) {
    const int warp = threadIdx.x >> 5;
    const int lane = threadIdx.x & 31;
    const int w    = blockIdx.x * 4 + warp;

    const int ql = lane >> 3;
    const int k  = lane & 7;

    const int q  = g_perm[w * 4 + ql];
    const int b  = q >> 2;
    const int t  = (q >> 1) & 1;
    const int es = q & 1;

    const float w0 = __ldg(w_lin + 0);
    const float w1 = __ldg(w_lin + 1);
    const float w2 = __ldg(w_lin + 2);
    const float w3 = __ldg(w_lin + 3);
    const float w4 = __ldg(w_lin + 4);
    const float w5 = __ldg(w_lin + 5);

    const float* p = phi + b * 20 + t * 10;
    const int x = (int)p[6 + 2 * es];
    const int y = (int)p[7 + 2 * es];

    const float* base = succ + ((size_t)(x * W_DIM + y)) * F_DIM
                             + (size_t)(k * 32) * S_STRIDE;

    float m = -3.0e38f, se = 0.0f, sev = 0.0f;

    for (int j0 = 0; j0 < 32; j0 += 4) {
#pragma unroll
        for (int u = 0; u < 4; u++) {
            const float* ptr = base + (size_t)(j0 + u) * S_STRIDE;
            const float2 a = __ldg((const float2*)(ptr + 0));
            const float2 c = __ldg((const float2*)(ptr + 2));
            const float2 d = __ldg((const float2*)(ptr + 4));
            const float v = fmaf(a.x, w0, fmaf(a.y, w1,
                            fmaf(c.x, w2, fmaf(c.y, w3,
                            fmaf(d.x, w4, d.y * w5)))));
            const float mo = m;
            m = fmaxf(m, v);
            const float corr = __expf(mo - m);
            const float e    = __expf(v - m);
            se  = fmaf(se,  corr, e);
            sev = fmaf(sev, corr, e * v);
        }
        __syncthreads();   // pace warps: keep block-level line reuse tight
    }

    // merge (m, se, sev) across the 8-lane group
#pragma unroll
    for (int off = 4; off > 0; off >>= 1) {
        const float m2   = __shfl_xor_sync(0xffffffffu, m,   off);
        const float se2  = __shfl_xor_sync(0xffffffffu, se,  off);
        const float sev2 = __shfl_xor_sync(0xffffffffu, sev, off);
        const float mm = fmaxf(m, m2);
        const float c1 = __expf(m  - mm);
        const float c2 = __expf(m2 - mm);
        se  = fmaf(se,  c1, se2  * c2);
        sev = fmaf(sev, c1, sev2 * c2);
        m = mm;
    }

    // group leader publishes; 4th arriver for b does the final combine.
    if (k == 0) {
        g_qv[q] = sev / se;
        __threadfence();                       // release
        const int old = atomicAdd(&g_done[b], 1);
        if (old == 3) {
            __threadfence();                   // acquire
            const float vss0 = g_qv[b * 4 + 0];
            const float ves0 = g_qv[b * 4 + 1];
            const float vss1 = g_qv[b * 4 + 2];
            const float ves1 = g_qv[b * 4 + 3];

            const float* p0 = phi + b * 20;
            const float* p1 = p0 + 10;
            const float pr0 = fmaf(p0[0], w0, fmaf(p0[1], w1, fmaf(p0[2], w2,
                              fmaf(p0[3], w3, fmaf(p0[4], w4, p0[5] * w5)))));
            const float pr1 = fmaf(p1[0], w0, fmaf(p1[1], w1, fmaf(p1[2], w2,
                              fmaf(p1[3], w3, fmaf(p1[4], w4, p1[5] * w5)))));

            const float left_der  = pr0 + (ves0 - vss0);
            const float right_der = pr1 + (ves1 - vss1);
            const float d = left_der - right_der;

            float2 r;
            r.x = 1.0f / (1.0f + expf(-d));
            r.y = 1.0f / (1.0f + expf(d));
            reinterpret_cast<float2*>(out)[b] = r;

            g_done[b] = 0;                     // restore for next graph replay
        }
    }
}

extern "C" void kernel_launch(void* const* d_in, const int* in_sizes, int n_in,
                              void* d_out, int out_size) {
    const float* phi   = (const float*)d_in[0];  // (B, 2, 10)
    const float* w_lin = (const float*)d_in[1];  // (1, 6)
    const float* succ  = (const float*)d_in[2];  // (S, H, W, F)
    float* out = (float*)d_out;                  // (B, 2, 1)

    k_hist<<<NQ / 128, 128>>>(phi);
    k_sortfin<<<1, 1024>>>();
    k_main<<<NQ / 16, 128>>>(phi, w_lin, succ, out);
}

// round 14
// speedup vs baseline: 1.3657x; 1.3657x over previous
#include <cuda_runtime.h>

#define S_DIM 256
#define H_DIM 256
#define W_DIM 256
#define F_DIM 6
#define B_DIM 4096
#define NQ (B_DIM * 4)          // 16384 queries, q = b*4 + t*2 + es
#define NBIN 4096               // sort key = (x<<4) | (y>>4)  (round-6 proven)
#define S_STRIDE (H_DIM * W_DIM * F_DIM)

__device__ int   g_perm[NQ];
__device__ float g_qv[NQ];
__device__ int   g_done[B_DIM]; // static zero-init; reset by the 4th arriver

// ---------- single-block counting sort of queries by (x, y/16) ----------
__global__ __launch_bounds__(1024)
void k_prep(const float* __restrict__ phi) {
    __shared__ int bin[NBIN];
    __shared__ int wsum[32];
    const int tid  = threadIdx.x;
    const int lane = tid & 31;
    const int wid  = tid >> 5;

    for (int i = tid; i < NBIN; i += 1024) bin[i] = 0;
    __syncthreads();

    int keys[16];
#pragma unroll
    for (int u = 0; u < 16; u++) {
        const int q  = tid + u * 1024;
        const int b  = q >> 2;
        const int t  = (q >> 1) & 1;
        const int es = q & 1;
        const float* p = phi + b * 20 + t * 10;
        const int x = (int)p[6 + 2 * es];
        const int y = (int)p[7 + 2 * es];
        keys[u] = (x << 4) | (y >> 4);
        atomicAdd(&bin[keys[u]], 1);
    }
    __syncthreads();

    // exclusive scan over bin[4096], 4 consecutive bins per thread
    const int base = tid * 4;
    const int c0 = bin[base], c1 = bin[base + 1];
    const int c2 = bin[base + 2], c3 = bin[base + 3];
    const int tsum = c0 + c1 + c2 + c3;

    int incl = tsum;
#pragma unroll
    for (int off = 1; off < 32; off <<= 1) {
        const int n = __shfl_up_sync(0xffffffffu, incl, off);
        if (lane >= off) incl += n;
    }
    if (lane == 31) wsum[wid] = incl;
    __syncthreads();
    if (wid == 0) {
        const int v = wsum[lane];
        int iv = v;
#pragma unroll
        for (int off = 1; off < 32; off <<= 1) {
            const int n = __shfl_up_sync(0xffffffffu, iv, off);
            if (lane >= off) iv += n;
        }
        wsum[lane] = iv - v;   // exclusive warp offsets
    }
    __syncthreads();

    const int excl = incl - tsum + wsum[wid];
    bin[base]     = excl;
    bin[base + 1] = excl + c0;
    bin[base + 2] = excl + c0 + c1;
    bin[base + 3] = excl + c0 + c1 + c2;
    __syncthreads();

    // scatter: g_perm[pos] = q (order within bin arbitrary -> values unaffected)
#pragma unroll
    for (int u = 0; u < 16; u++) {
        const int q   = tid + u * 1024;
        const int pos = atomicAdd(&bin[keys[u]], 1);
        g_perm[pos] = q;
    }
}

// ---------- main gather: warp = 4 consecutive sorted queries x 8 s-lanes ----------
// lane = ql*8 + k; thread owns s = 32k + j, j=0..31. Sorted same-line queries
// share one load instruction -> warp coalescer merges into ~1 line request.
__global__ __launch_bounds__(128, 8)
void k_main(const float* __restrict__ phi,
            const float* __restrict__ w_lin,
            const float* __restrict__ succ,
            float* __restrict__ out) {
    const int warp = threadIdx.x >> 5;
    const int lane = threadIdx.x & 31;
    const int w    = blockIdx.x * 4 + warp;

    const int ql = lane >> 3;
    const int k  = lane & 7;

    const int q  = g_perm[w * 4 + ql];
    const int b  = q >> 2;
    const int t  = (q >> 1) & 1;
    const int es = q & 1;

    const float w0 = __ldg(w_lin + 0);
    const float w1 = __ldg(w_lin + 1);
    const float w2 = __ldg(w_lin + 2);
    const float w3 = __ldg(w_lin + 3);
    const float w4 = __ldg(w_lin + 4);
    const float w5 = __ldg(w_lin + 5);

    const float* p = phi + b * 20 + t * 10;
    const int x = (int)p[6 + 2 * es];
    const int y = (int)p[7 + 2 * es];

    const float* base = succ + ((size_t)(x * W_DIM + y)) * F_DIM
                             + (size_t)(k * 32) * S_STRIDE;

    float m = -3.0e38f, se = 0.0f, sev = 0.0f;

    for (int j0 = 0; j0 < 32; j0 += 4) {
#pragma unroll
        for (int u = 0; u < 4; u++) {
            const float* ptr = base + (size_t)(j0 + u) * S_STRIDE;
            const float2 a = __ldg((const float2*)(ptr + 0));
            const float2 c = __ldg((const float2*)(ptr + 2));
            const float2 d = __ldg((const float2*)(ptr + 4));
            const float v = fmaf(a.x, w0, fmaf(a.y, w1,
                            fmaf(c.x, w2, fmaf(c.y, w3,
                            fmaf(d.x, w4, d.y * w5)))));
            const float mo = m;
            m = fmaxf(m, v);
            const float corr = __expf(mo - m);
            const float e    = __expf(v - m);
            se  = fmaf(se,  corr, e);
            sev = fmaf(sev, corr, e * v);
        }
        __syncthreads();   // pace warps: keep the block's line reuse tight
    }

    // merge (m, se, sev) across the 8-lane group
#pragma unroll
    for (int off = 4; off > 0; off >>= 1) {
        const float m2   = __shfl_xor_sync(0xffffffffu, m,   off);
        const float se2  = __shfl_xor_sync(0xffffffffu, se,  off);
        const float sev2 = __shfl_xor_sync(0xffffffffu, sev, off);
        const float mm = fmaxf(m, m2);
        const float c1 = __expf(m  - mm);
        const float c2 = __expf(m2 - mm);
        se  = fmaf(se,  c1, se2  * c2);
        sev = fmaf(sev, c1, sev2 * c2);
        m = mm;
    }

    // group leader publishes; 4th arriver for b does the final combine.
    if (k == 0) {
        g_qv[q] = sev / se;
        __threadfence();                       // release
        const int old = atomicAdd(&g_done[b], 1);
        if (old == 3) {
            __threadfence();                   // acquire
            const float vss0 = g_qv[b * 4 + 0];
            const float ves0 = g_qv[b * 4 + 1];
            const float vss1 = g_qv[b * 4 + 2];
            const float ves1 = g_qv[b * 4 + 3];

            const float* p0 = phi + b * 20;
            const float* p1 = p0 + 10;
            const float pr0 = fmaf(p0[0], w0, fmaf(p0[1], w1, fmaf(p0[2], w2,
                              fmaf(p0[3], w3, fmaf(p0[4], w4, p0[5] * w5)))));
            const float pr1 = fmaf(p1[0], w0, fmaf(p1[1], w1, fmaf(p1[2], w2,
                              fmaf(p1[3], w3, fmaf(p1[4], w4, p1[5] * w5)))));

            const float left_der  = pr0 + (ves0 - vss0);
            const float right_der = pr1 + (ves1 - vss1);
            const float d = left_der - right_der;

            float2 r;
            r.x = 1.0f / (1.0f + expf(-d));
            r.y = 1.0f / (1.0f + expf(d));
            reinterpret_cast<float2*>(out)[b] = r;

            g_done[b] = 0;                     // restore for next graph replay
        }
    }
}

extern "C" void kernel_launch(void* const* d_in, const int* in_sizes, int n_in,
                              void* d_out, int out_size) {
    const float* phi   = (const float*)d_in[0];  // (B, 2, 10)
    const float* w_lin = (const float*)d_in[1];  // (1, 6)
    const float* succ  = (const float*)d_in[2];  // (S, H, W, F)
    float* out = (float*)d_out;                  // (B, 2, 1)

    k_prep<<<1, 1024>>>(phi);
    k_main<<<NQ / 16, 128>>>(phi, w_lin, succ, out);
}

// round 15
// speedup vs baseline: 1.3742x; 1.0062x over previous
#include <cuda_runtime.h>

#define S_DIM 256
#define H_DIM 256
#define W_DIM 256
#define F_DIM 6
#define B_DIM 4096
#define NQ (B_DIM * 4)          // 16384 queries, q = b*4 + t*2 + es
#define NBIN 4096               // sort key = (x<<4) | (y>>4)  (round-6 proven)
#define S_STRIDE (H_DIM * W_DIM * F_DIM)

__device__ int   g_perm[NQ];
__device__ float g_qv[NQ];
__device__ int   g_done[B_DIM]; // static zero-init; reset by the 4th arriver

// ---------- single-block counting sort of queries by (x, y/16) ----------
__global__ __launch_bounds__(1024)
void k_prep(const float* __restrict__ phi) {
    __shared__ int bin[NBIN];
    __shared__ int wsum[32];
    const int tid  = threadIdx.x;
    const int lane = tid & 31;
    const int wid  = tid >> 5;

    for (int i = tid; i < NBIN; i += 1024) bin[i] = 0;
    __syncthreads();

    int keys[16];
#pragma unroll
    for (int u = 0; u < 16; u++) {
        const int q  = tid + u * 1024;
        const int b  = q >> 2;
        const int t  = (q >> 1) & 1;
        const int es = q & 1;
        const float* p = phi + b * 20 + t * 10;
        const int x = (int)p[6 + 2 * es];
        const int y = (int)p[7 + 2 * es];
        keys[u] = (x << 4) | (y >> 4);
        atomicAdd(&bin[keys[u]], 1);
    }
    __syncthreads();

    // exclusive scan over bin[4096], 4 consecutive bins per thread
    const int base = tid * 4;
    const int c0 = bin[base], c1 = bin[base + 1];
    const int c2 = bin[base + 2], c3 = bin[base + 3];
    const int tsum = c0 + c1 + c2 + c3;

    int incl = tsum;
#pragma unroll
    for (int off = 1; off < 32; off <<= 1) {
        const int n = __shfl_up_sync(0xffffffffu, incl, off);
        if (lane >= off) incl += n;
    }
    if (lane == 31) wsum[wid] = incl;
    __syncthreads();
    if (wid == 0) {
        const int v = wsum[lane];
        int iv = v;
#pragma unroll
        for (int off = 1; off < 32; off <<= 1) {
            const int n = __shfl_up_sync(0xffffffffu, iv, off);
            if (lane >= off) iv += n;
        }
        wsum[lane] = iv - v;   // exclusive warp offsets
    }
    __syncthreads();

    const int excl = incl - tsum + wsum[wid];
    bin[base]     = excl;
    bin[base + 1] = excl + c0;
    bin[base + 2] = excl + c0 + c1;
    bin[base + 3] = excl + c0 + c1 + c2;
    __syncthreads();

    // scatter: g_perm[pos] = q (order within bin arbitrary -> values unaffected)
#pragma unroll
    for (int u = 0; u < 16; u++) {
        const int q   = tid + u * 1024;
        const int pos = atomicAdd(&bin[keys[u]], 1);
        g_perm[pos] = q;
    }
}

// ---------- main gather: warp = 4 consecutive sorted queries x 8 s-lanes ----------
// lane = ql*8 + k; thread owns s = 32k + j, j=0..31. Sorted same-line queries
// share one load instruction -> warp coalescer merges into ~1 line request.
__global__ __launch_bounds__(128, 8)
void k_main(const float* __restrict__ phi,
            const float* __restrict__ w_lin,
            const float* __restrict__ succ,
            float* __restrict__ out) {
    const int warp = threadIdx.x >> 5;
    const int lane = threadIdx.x & 31;
    const int w    = blockIdx.x * 4 + warp;

    const int ql = lane >> 3;
    const int k  = lane & 7;

    const int q  = g_perm[w * 4 + ql];
    const int b  = q >> 2;
    const int t  = (q >> 1) & 1;
    const int es = q & 1;

    const float w0 = __ldg(w_lin + 0);
    const float w1 = __ldg(w_lin + 1);
    const float w2 = __ldg(w_lin + 2);
    const float w3 = __ldg(w_lin + 3);
    const float w4 = __ldg(w_lin + 4);
    const float w5 = __ldg(w_lin + 5);

    const float* p = phi + b * 20 + t * 10;
    const int x = (int)p[6 + 2 * es];
    const int y = (int)p[7 + 2 * es];

    const float* base = succ + ((size_t)(x * W_DIM + y)) * F_DIM
                             + (size_t)(k * 32) * S_STRIDE;

    float m = -3.0e38f, se = 0.0f, sev = 0.0f;

    for (int j0 = 0; j0 < 32; j0 += 4) {
#pragma unroll
        for (int u = 0; u < 4; u++) {
            const float* ptr = base + (size_t)(j0 + u) * S_STRIDE;
            const float2 a = __ldg((const float2*)(ptr + 0));
            const float2 c = __ldg((const float2*)(ptr + 2));
            const float2 d = __ldg((const float2*)(ptr + 4));
            const float v = fmaf(a.x, w0, fmaf(a.y, w1,
                            fmaf(c.x, w2, fmaf(c.y, w3,
                            fmaf(d.x, w4, d.y * w5)))));
            const float mo = m;
            m = fmaxf(m, v);
            const float corr = __expf(mo - m);
            const float e    = __expf(v - m);
            se  = fmaf(se,  corr, e);
            sev = fmaf(sev, corr, e * v);
        }
        __syncthreads();   // pace warps: keep the block's line reuse tight
    }

    // merge (m, se, sev) across the 8-lane group
#pragma unroll
    for (int off = 4; off > 0; off >>= 1) {
        const float m2   = __shfl_xor_sync(0xffffffffu, m,   off);
        const float se2  = __shfl_xor_sync(0xffffffffu, se,  off);
        const float sev2 = __shfl_xor_sync(0xffffffffu, sev, off);
        const float mm = fmaxf(m, m2);
        const float c1 = __expf(m  - mm);
        const float c2 = __expf(m2 - mm);
        se  = fmaf(se,  c1, se2  * c2);
        sev = fmaf(sev, c1, sev2 * c2);
        m = mm;
    }

    // Group leader publishes its value, then does a RELEASE atomic (no L1
    // flush — unlike __threadfence, which emits CCTL.IVALL on sm_103a and
    // wrecks the L1 reuse the sort creates). The 4th arriver reads the four
    // values via L2 (__ldcg: always fresh, no acquire/invalidate needed since
    // these addresses were never read into this SM's L1).
    if (k == 0) {
        g_qv[q] = sev / se;   // write-through to L2
        int old;
        asm volatile("atom.release.gpu.global.add.s32 %0, [%1], 1;"
                     : "=r"(old) : "l"(&g_done[b]) : "memory");
        if (old == 3) {
            const float vss0 = __ldcg(&g_qv[b * 4 + 0]);
            const float ves0 = __ldcg(&g_qv[b * 4 + 1]);
            const float vss1 = __ldcg(&g_qv[b * 4 + 2]);
            const float ves1 = __ldcg(&g_qv[b * 4 + 3]);

            const float* p0 = phi + b * 20;
            const float* p1 = p0 + 10;
            const float pr0 = fmaf(p0[0], w0, fmaf(p0[1], w1, fmaf(p0[2], w2,
                              fmaf(p0[3], w3, fmaf(p0[4], w4, p0[5] * w5)))));
            const float pr1 = fmaf(p1[0], w0, fmaf(p1[1], w1, fmaf(p1[2], w2,
                              fmaf(p1[3], w3, fmaf(p1[4], w4, p1[5] * w5)))));

            const float left_der  = pr0 + (ves0 - vss0);
            const float right_der = pr1 + (ves1 - vss1);
            const float d = left_der - right_der;

            float2 r;
            r.x = 1.0f / (1.0f + expf(-d));
            r.y = 1.0f / (1.0f + expf(d));
            reinterpret_cast<float2*>(out)[b] = r;

            g_done[b] = 0;   // restore for next graph replay (cross-kernel order)
        }
    }
}

extern "C" void kernel_launch(void* const* d_in, const int* in_sizes, int n_in,
                              void* d_out, int out_size) {
    const float* phi   = (const float*)d_in[0];  // (B, 2, 10)
    const float* w_lin = (const float*)d_in[1];  // (1, 6)
    const float* succ  = (const float*)d_in[2];  // (S, H, W, F)
    float* out = (float*)d_out;                  // (B, 2, 1)

    k_prep<<<1, 1024>>>(phi);
    k_main<<<NQ / 16, 128>>>(phi, w_lin, succ, out);
}

// round 16
// speedup vs baseline: 1.4146x; 1.0294x over previous
#include <cuda_runtime.h>

#define S_DIM 256
#define H_DIM 256
#define W_DIM 256
#define F_DIM 6
#define B_DIM 4096
#define NQ (B_DIM * 4)          // 16384 queries, q = b*4 + t*2 + es
#define NBIN 4096               // sort key = (x<<4) | (y>>4)  (round-6 proven)
#define S_STRIDE (H_DIM * W_DIM * F_DIM)

__device__ int   g_bin[NBIN];   // static zero-init; k_sortfin re-zeroes each call
__device__ int   g_keys[NQ];
__device__ int   g_perm[NQ];
__device__ float g_qv[NQ];
__device__ int   g_done[B_DIM]; // static zero-init; reset by the 4th arriver

__device__ __forceinline__ int query_key(const float* __restrict__ phi, int q) {
    const int b  = q >> 2;
    const int t  = (q >> 1) & 1;
    const int es = q & 1;
    const float* p = phi + b * 20 + t * 10;
    const int x = (int)p[6 + 2 * es];
    const int y = (int)p[7 + 2 * es];
    return (x << 4) | (y >> 4);
}

// ---------- phase A: keys + global histogram (parallel, measured ~4.3us) ----------
__global__ __launch_bounds__(128)
void k_hist(const float* __restrict__ phi) {
    const int q = blockIdx.x * 128 + threadIdx.x;
    const int key = query_key(phi, q);
    g_keys[q] = key;
    atomicAdd(&g_bin[key], 1);
}

// ---------- phase B: fused scan + scatter, one block, 4096 bins in smem ----------
__global__ __launch_bounds__(1024)
void k_sortfin() {
    __shared__ int bin[NBIN];    // 16 KB
    __shared__ int wsum[32];
    const int tid  = threadIdx.x;
    const int lane = tid & 31;
    const int wid  = tid >> 5;
    const int base = tid * 4;

    const int c0 = g_bin[base + 0];
    const int c1 = g_bin[base + 1];
    const int c2 = g_bin[base + 2];
    const int c3 = g_bin[base + 3];
    g_bin[base + 0] = 0;         // restore invariant for the next graph replay
    g_bin[base + 1] = 0;
    g_bin[base + 2] = 0;
    g_bin[base + 3] = 0;
    const int tsum = c0 + c1 + c2 + c3;

    int incl = tsum;
#pragma unroll
    for (int off = 1; off < 32; off <<= 1) {
        const int n = __shfl_up_sync(0xffffffffu, incl, off);
        if (lane >= off) incl += n;
    }
    if (lane == 31) wsum[wid] = incl;
    __syncthreads();
    if (wid == 0) {
        const int v = wsum[lane];
        int iv = v;
#pragma unroll
        for (int off = 1; off < 32; off <<= 1) {
            const int n = __shfl_up_sync(0xffffffffu, iv, off);
            if (lane >= off) iv += n;
        }
        wsum[lane] = iv - v;     // exclusive warp offsets
    }
    __syncthreads();

    const int excl = incl - tsum + wsum[wid];
    bin[base + 0] = excl;
    bin[base + 1] = excl + c0;
    bin[base + 2] = excl + c0 + c1;
    bin[base + 3] = excl + c0 + c1 + c2;
    __syncthreads();

    // scatter: 16 queries per thread; smem-atomic slots
#pragma unroll
    for (int u = 0; u < 16; u++) {
        const int q   = tid + u * 1024;
        const int pos = atomicAdd(&bin[g_keys[q]], 1);
        g_perm[pos] = q;
    }
}

// ---------- main gather ----------
// Warp pair per query-quad: warp layout inside each warp is UNCHANGED
// (4 consecutive sorted queries x 8 s-lanes -> coalescer dedup preserved),
// but half=warp&1 covers s-planes [half*128, half*128+128). 8192 warps ->
// the 8-block/SM reg cap is fully used (occ ~50% vs 37.8% grid-limited).
__global__ __launch_bounds__(128, 8)
void k_main(const float* __restrict__ phi,
            const float* __restrict__ w_lin,
            const float* __restrict__ succ,
            float* __restrict__ out) {
    const int warp = threadIdx.x >> 5;   // 0..3
    const int lane = threadIdx.x & 31;
    const int pair = warp >> 1;          // quad index within block (0..1)
    const int half = warp & 1;           // s-range half
    const int w    = blockIdx.x * 2 + pair;

    const int ql = lane >> 3;            // 0..3: query within quad
    const int k  = lane & 7;             // s chunk id

    const int q  = g_perm[w * 4 + ql];
    const int b  = q >> 2;
    const int t  = (q >> 1) & 1;
    const int es = q & 1;

    const float w0 = __ldg(w_lin + 0);
    const float w1 = __ldg(w_lin + 1);
    const float w2 = __ldg(w_lin + 2);
    const float w3 = __ldg(w_lin + 3);
    const float w4 = __ldg(w_lin + 4);
    const float w5 = __ldg(w_lin + 5);

    const float* p = phi + b * 20 + t * 10;
    const int x = (int)p[6 + 2 * es];
    const int y = (int)p[7 + 2 * es];

    // thread owns s = k*32 + half*16 + j, j=0..15
    const float* base = succ + ((size_t)(x * W_DIM + y)) * F_DIM
                             + (size_t)(k * 32 + half * 16) * S_STRIDE;

    float m = -3.0e38f, se = 0.0f, sev = 0.0f;

    for (int j0 = 0; j0 < 16; j0 += 4) {
#pragma unroll
        for (int u = 0; u < 4; u++) {
            const float* ptr = base + (size_t)(j0 + u) * S_STRIDE;
            const float2 a = __ldg((const float2*)(ptr + 0));
            const float2 c = __ldg((const float2*)(ptr + 2));
            const float2 d = __ldg((const float2*)(ptr + 4));
            const float v = fmaf(a.x, w0, fmaf(a.y, w1,
                            fmaf(c.x, w2, fmaf(c.y, w3,
                            fmaf(d.x, w4, d.y * w5)))));
            const float mo = m;
            m = fmaxf(m, v);
            const float corr = __expf(mo - m);
            const float e    = __expf(v - m);
            se  = fmaf(se,  corr, e);
            sev = fmaf(sev, corr, e * v);
        }
        __syncthreads();   // pace warps: keep the block's line reuse tight
    }

    // merge (m, se, sev) across the 8-lane group
#pragma unroll
    for (int off = 4; off > 0; off >>= 1) {
        const float m2   = __shfl_xor_sync(0xffffffffu, m,   off);
        const float se2  = __shfl_xor_sync(0xffffffffu, se,  off);
        const float sev2 = __shfl_xor_sync(0xffffffffu, sev, off);
        const float mm = fmaxf(m, m2);
        const float c1 = __expf(m  - mm);
        const float c2 = __expf(m2 - mm);
        se  = fmaf(se,  c1, se2  * c2);
        sev = fmaf(sev, c1, sev2 * c2);
        m = mm;
    }

    // cross-half merge through smem: half 1 publishes, half 0 finishes.
    __shared__ float s_m[8], s_se[8], s_sev[8];   // [pair*4 + ql]
    const int gi = pair * 4 + ql;
    if (half == 1 && k == 0) {
        s_m[gi] = m; s_se[gi] = se; s_sev[gi] = sev;
    }
    __syncthreads();

    if (half == 0 && k == 0) {
        const float m2 = s_m[gi], se2 = s_se[gi], sev2 = s_sev[gi];
        const float mm = fmaxf(m, m2);
        const float c1 = __expf(m  - mm);
        const float c2 = __expf(m2 - mm);
        se  = fmaf(se,  c1, se2  * c2);
        sev = fmaf(sev, c1, sev2 * c2);

        g_qv[q] = sev / se;   // write-through to L2
        int old;
        asm volatile("atom.release.gpu.global.add.s32 %0, [%1], 1;"
                     : "=r"(old) : "l"(&g_done[b]) : "memory");
        if (old == 3) {
            const float vss0 = __ldcg(&g_qv[b * 4 + 0]);
            const float ves0 = __ldcg(&g_qv[b * 4 + 1]);
            const float vss1 = __ldcg(&g_qv[b * 4 + 2]);
            const float ves1 = __ldcg(&g_qv[b * 4 + 3]);

            const float* p0 = phi + b * 20;
            const float* p1 = p0 + 10;
            const float pr0 = fmaf(p0[0], w0, fmaf(p0[1], w1, fmaf(p0[2], w2,
                              fmaf(p0[3], w3, fmaf(p0[4], w4, p0[5] * w5)))));
            const float pr1 = fmaf(p1[0], w0, fmaf(p1[1], w1, fmaf(p1[2], w2,
                              fmaf(p1[3], w3, fmaf(p1[4], w4, p1[5] * w5)))));

            const float left_der  = pr0 + (ves0 - vss0);
            const float right_der = pr1 + (ves1 - vss1);
            const float d = left_der - right_der;

            float2 r;
            r.x = 1.0f / (1.0f + expf(-d));
            r.y = 1.0f / (1.0f + expf(d));
            reinterpret_cast<float2*>(out)[b] = r;

            g_done[b] = 0;   // restore for next graph replay
        }
    }
}

extern "C" void kernel_launch(void* const* d_in, const int* in_sizes, int n_in,
                              void* d_out, int out_size) {
    const float* phi   = (const float*)d_in[0];  // (B, 2, 10)
    const float* w_lin = (const float*)d_in[1];  // (1, 6)
    const float* succ  = (const float*)d_in[2];  // (S, H, W, F)
    float* out = (float*)d_out;                  // (B, 2, 1)

    k_hist<<<NQ / 128, 128>>>(phi);
    k_sortfin<<<1, 1024>>>();
    k_main<<<NQ / 8, 128>>>(phi, w_lin, succ, out);
}